// round 2
// baseline (speedup 1.0000x reference)
#include <cuda_runtime.h>
#include <math.h>

#define Bv 8
#define Tv 2048
#define Cv 1024
#define HSv 64
#define Mv (Bv*Tv)           // 16384 total rows
#define SPLITS 2
#define KCHUNK 1024
#define QT 128               // query rows per attention block
#define KT 32                // keys per smem tile

typedef unsigned long long u64;

// ---------- f32x2 packed-math helpers (sm_100+ PTX; doubles FFMA rate) ----------
__device__ __forceinline__ u64 pack2(float a, float b){
    u64 r; asm("mov.b64 %0, {%1, %2};" : "=l"(r) : "f"(a), "f"(b)); return r;
}
__device__ __forceinline__ void unpack2(u64 v, float &a, float &b){
    asm("mov.b64 {%0, %1}, %2;" : "=f"(a), "=f"(b) : "l"(v));
}
__device__ __forceinline__ u64 ffma2(u64 a, u64 b, u64 c){
    u64 d; asm("fma.rn.f32x2 %0, %1, %2, %3;" : "=l"(d) : "l"(a), "l"(b), "l"(c)); return d;
}
__device__ __forceinline__ u64 fmul2(u64 a, u64 b){
    u64 d; asm("mul.rn.f32x2 %0, %1, %2;" : "=l"(d) : "l"(a), "l"(b)); return d;
}

// ---------- scratch (static device arrays: no allocations allowed) ----------
__device__ float g_qkv[3*Mv*HSv];          // projected q, k, v  (12.6 MB)
__device__ float g_pacc[SPLITS*Mv*HSv];    // split-K partial accumulators (8.4 MB)
__device__ float g_pm[SPLITS*Mv];          // partial row max
__device__ float g_pl[SPLITS*Mv];          // partial row sum

// =====================================================================
// Kernel 1: fused projections  out[z] = X[z] @ W[z]   (z = q,k,v)
// M-tile 128 x N 64, K chunks of 32, gmem->reg prefetch, f32x2 math.
// =====================================================================
__global__ __launch_bounds__(256) void proj_kernel(
    const float* __restrict__ qv, const float* __restrict__ kvec,
    const float* __restrict__ vv,
    const float* __restrict__ Wq, const float* __restrict__ Wk,
    const float* __restrict__ Wv)
{
    __shared__ float As[128*36];   // 128 rows x 32 k, padded stride 36
    __shared__ float Ws[32*64];    // 32 k x 64 n

    const int z = blockIdx.y;
    const float* A = (z==0) ? qv : (z==1) ? kvec : vv;
    const float* W = (z==0) ? Wq : (z==1) ? Wk : Wv;
    float* out = g_qkv + (size_t)z * Mv * HSv;

    const int t  = threadIdx.x;
    const int m0 = blockIdx.x * 128;
    const int tx = t & 7;          // col group: cols tx*8 .. tx*8+7
    const int ty = t >> 3;         // row group: rows ty*4 .. ty*4+3

    float4 aPre[4], wPre[2];
    #pragma unroll
    for (int i = 0; i < 4; i++){
        int idx = t + i*256; int r = idx >> 3, c4 = idx & 7;
        aPre[i] = *(const float4*)(A + (size_t)(m0 + r)*Cv + c4*4);
    }
    #pragma unroll
    for (int i = 0; i < 2; i++){
        int idx = t + i*256; int r = idx >> 4, c4 = idx & 15;
        wPre[i] = *(const float4*)(W + (size_t)r*HSv + c4*4);
    }

    u64 acc[4][4];
    const u64 z2 = pack2(0.f, 0.f);
    #pragma unroll
    for (int i = 0; i < 4; i++)
        #pragma unroll
        for (int j = 0; j < 4; j++) acc[i][j] = z2;

    #pragma unroll 1
    for (int kc = 0; kc < Cv/32; kc++){
        #pragma unroll
        for (int i = 0; i < 4; i++){
            int idx = t + i*256; int r = idx >> 3, c4 = idx & 7;
            *(float4*)(As + r*36 + c4*4) = aPre[i];
        }
        #pragma unroll
        for (int i = 0; i < 2; i++){
            int idx = t + i*256; int r = idx >> 4, c4 = idx & 15;
            *(float4*)(Ws + r*64 + c4*4) = wPre[i];
        }
        __syncthreads();

        if (kc + 1 < Cv/32){           // prefetch next chunk (overlaps compute)
            int kk0 = (kc + 1) * 32;
            #pragma unroll
            for (int i = 0; i < 4; i++){
                int idx = t + i*256; int r = idx >> 3, c4 = idx & 7;
                aPre[i] = *(const float4*)(A + (size_t)(m0 + r)*Cv + kk0 + c4*4);
            }
            #pragma unroll
            for (int i = 0; i < 2; i++){
                int idx = t + i*256; int r = idx >> 4, c4 = idx & 15;
                wPre[i] = *(const float4*)(W + (size_t)(kk0 + r)*HSv + c4*4);
            }
        }

        #pragma unroll
        for (int kk = 0; kk < 32; kk++){
            const ulonglong2* wr = (const ulonglong2*)(Ws + kk*64 + tx*8);
            ulonglong2 w01 = wr[0];
            ulonglong2 w23 = wr[1];
            #pragma unroll
            for (int i = 0; i < 4; i++){
                float a = As[(ty*4 + i)*36 + kk];
                u64 ap = pack2(a, a);
                acc[i][0] = ffma2(ap, w01.x, acc[i][0]);
                acc[i][1] = ffma2(ap, w01.y, acc[i][1]);
                acc[i][2] = ffma2(ap, w23.x, acc[i][2]);
                acc[i][3] = ffma2(ap, w23.y, acc[i][3]);
            }
        }
        __syncthreads();
    }

    #pragma unroll
    for (int i = 0; i < 4; i++){
        u64* orow = (u64*)(out + (size_t)(m0 + ty*4 + i)*HSv + tx*8);
        orow[0] = acc[i][0]; orow[1] = acc[i][1];
        orow[2] = acc[i][2]; orow[3] = acc[i][3];
    }
}

// =====================================================================
// Kernel 2: causal flash attention, fp32, split-K over 2 key chunks.
// One query row per thread; 128-row q-tiles; KT=32 key tiles in smem.
// =====================================================================
__global__ __launch_bounds__(128) void attn_kernel(const int* __restrict__ mask)
{
    const int qb = blockIdx.x;          // q-tile index 0..15
    const int s  = blockIdx.y;          // key chunk 0..1
    const int b  = blockIdx.z;          // batch
    const int t  = threadIdx.x;
    const int r    = qb*QT + t;         // this thread's query row in [0,T)
    const int bT   = b*Tv;
    const int rowg = bT + r;
    const int k0   = s*KCHUNK;
    const int qend = qb*QT + QT;        // block's max key bound

    // whole block has no keys in this chunk -> emit empty partial
    if (k0 >= qend){
        g_pm[s*Mv + rowg] = -INFINITY;
        g_pl[s*Mv + rowg] = 0.f;
        float4 zz = make_float4(0.f,0.f,0.f,0.f);
        float4* pa = (float4*)(g_pacc + (size_t)(s*Mv + rowg)*HSv);
        #pragma unroll
        for (int i = 0; i < 16; i++) pa[i] = zz;
        return;
    }

    const float* Qp = g_qkv;
    const float* Kp = g_qkv + (size_t)Mv*HSv;
    const float* Vp = g_qkv + 2*(size_t)Mv*HSv;

    __shared__ float Ks[KT*64];
    __shared__ float Vs[KT*64];
    __shared__ int   Ms[KT];

    // load my query row, pre-scaled by HS^-0.5 = 0.125, into packed regs
    u64 qp[32];
    {
        const u64 sc2 = pack2(0.125f, 0.125f);
        const ulonglong2* qr = (const ulonglong2*)(Qp + (size_t)rowg*HSv);
        #pragma unroll
        for (int c = 0; c < 16; c++){
            ulonglong2 u = qr[c];
            qp[2*c]   = fmul2(u.x, sc2);
            qp[2*c+1] = fmul2(u.y, sc2);
        }
    }

    u64 acc[32];
    #pragma unroll
    for (int c = 0; c < 32; c++) acc[c] = pack2(0.f, 0.f);
    float m = -INFINITY, l = 0.f;

    const int kend = min(k0 + KCHUNK, qend);
    const int nt = (kend - k0) >> 5;    // tiles of 32 (always exact)

    // prefetch tile 0
    float4 kreg[4], vreg[4]; int mreg = 1;
    {
        #pragma unroll
        for (int i = 0; i < 4; i++){
            int idx = t + i*128; int row = idx >> 4, c4 = idx & 15;
            kreg[i] = *(const float4*)(Kp + (size_t)(bT + k0 + row)*HSv + c4*4);
            vreg[i] = *(const float4*)(Vp + (size_t)(bT + k0 + row)*HSv + c4*4);
        }
        if (t < KT) mreg = mask[bT + k0 + t];
    }

    #pragma unroll 1
    for (int tt = 0; tt < nt; tt++){
        const int kt0 = k0 + tt*KT;
        __syncthreads();                 // previous tile fully consumed
        #pragma unroll
        for (int i = 0; i < 4; i++){
            int idx = t + i*128; int row = idx >> 4, c4 = idx & 15;
            *(float4*)(Ks + row*64 + c4*4) = kreg[i];
            *(float4*)(Vs + row*64 + c4*4) = vreg[i];
        }
        if (t < KT) Ms[t] = mreg;
        __syncthreads();

        if (tt + 1 < nt){                // prefetch next tile during compute
            int kn = kt0 + KT;
            #pragma unroll
            for (int i = 0; i < 4; i++){
                int idx = t + i*128; int row = idx >> 4, c4 = idx & 15;
                kreg[i] = *(const float4*)(Kp + (size_t)(bT + kn + row)*HSv + c4*4);
                vreg[i] = *(const float4*)(Vp + (size_t)(bT + kn + row)*HSv + c4*4);
            }
            if (t < KT) mreg = mask[bT + kn + t];
        }

        const int lim = r - kt0;         // keys j <= lim are causally valid
        if (lim >= 0){
            float sj[KT];
            #pragma unroll
            for (int j = 0; j < KT; j++){
                const ulonglong2* kr = (const ulonglong2*)(Ks + j*64);
                u64 a0 = pack2(0.f,0.f), a1 = pack2(0.f,0.f);
                #pragma unroll
                for (int c = 0; c < 16; c++){
                    ulonglong2 k2 = kr[c];
                    a0 = ffma2(qp[2*c],   k2.x, a0);
                    a1 = ffma2(qp[2*c+1], k2.y, a1);
                }
                float x0,x1,y0,y1;
                unpack2(a0, x0, x1); unpack2(a1, y0, y1);
                float dot = (x0 + y0) + (x1 + y1);
                sj[j] = (j <= lim && Ms[j]) ? dot : -INFINITY;
            }
            float tm = -INFINITY;
            #pragma unroll
            for (int j = 0; j < KT; j++) tm = fmaxf(tm, sj[j]);
            float mn = fmaxf(m, tm);
            if (mn > -INFINITY){
                float corr = __expf(m - mn);     // exp(-inf)=0 handles first tile
                u64 c2 = pack2(corr, corr);
                #pragma unroll
                for (int c = 0; c < 32; c++) acc[c] = fmul2(acc[c], c2);
                float ls = 0.f;
                #pragma unroll
                for (int j = 0; j < KT; j++){ sj[j] = __expf(sj[j] - mn); ls += sj[j]; }
                l = l*corr + ls;
                m = mn;
                #pragma unroll
                for (int j = 0; j < KT; j++){
                    u64 pj = pack2(sj[j], sj[j]);
                    const ulonglong2* vr = (const ulonglong2*)(Vs + j*64);
                    #pragma unroll
                    for (int c = 0; c < 16; c++){
                        ulonglong2 v2 = vr[c];
                        acc[2*c]   = ffma2(pj, v2.x, acc[2*c]);
                        acc[2*c+1] = ffma2(pj, v2.y, acc[2*c+1]);
                    }
                }
            }
        }
    }

    // write unnormalized partials
    g_pm[s*Mv + rowg] = m;
    g_pl[s*Mv + rowg] = l;
    u64* pa = (u64*)(g_pacc + (size_t)(s*Mv + rowg)*HSv);
    #pragma unroll
    for (int c = 0; c < 32; c++) pa[c] = acc[c];
}

// =====================================================================
// Kernel 3: merge split-K partials -> final output
// =====================================================================
__global__ __launch_bounds__(256) void merge_kernel(float* __restrict__ out)
{
    int gid = blockIdx.x * blockDim.x + threadIdx.x;   // Mv*16 threads
    int row = gid >> 4, c4 = gid & 15;
    float m0 = g_pm[row],      m1 = g_pm[Mv + row];
    float l0 = g_pl[row],      l1 = g_pl[Mv + row];
    float M  = fmaxf(m0, m1);
    float4 o = make_float4(0.f, 0.f, 0.f, 0.f);
    if (M > -INFINITY){
        float w0 = __expf(m0 - M), w1 = __expf(m1 - M);
        float denom = l0*w0 + l1*w1;
        float inv = (denom > 0.f) ? 1.f/denom : 0.f;
        float4 a0 = ((const float4*)g_pacc)[(size_t)row*16 + c4];
        float4 a1 = ((const float4*)(g_pacc + (size_t)Mv*HSv))[(size_t)row*16 + c4];
        o.x = (a0.x*w0 + a1.x*w1)*inv;
        o.y = (a0.y*w0 + a1.y*w1)*inv;
        o.z = (a0.z*w0 + a1.z*w1)*inv;
        o.w = (a0.w*w0 + a1.w*w1)*inv;
    }
    ((float4*)out)[gid] = o;
}

// =====================================================================
extern "C" void kernel_launch(void* const* d_in, const int* in_sizes, int n_in,
                              void* d_out, int out_size)
{
    const float* q_vec = (const float*)d_in[0];
    const float* k_vec = (const float*)d_in[1];
    const float* v_vec = (const float*)d_in[2];
    const int*   mask  = (const int*)  d_in[3];
    const float* Wq    = (const float*)d_in[4];
    const float* Wk    = (const float*)d_in[5];
    const float* Wv    = (const float*)d_in[6];
    float* out = (float*)d_out;

    proj_kernel<<<dim3(Mv/128, 3), 256>>>(q_vec, k_vec, v_vec, Wq, Wk, Wv);
    attn_kernel<<<dim3(Tv/QT, SPLITS, Bv), QT>>>(mask);
    merge_kernel<<<(Mv*16)/256, 256>>>(out);
}

// round 3
// speedup vs baseline: 1.5557x; 1.5557x over previous
#include <cuda_runtime.h>
#include <math.h>

#define Bv 8
#define Tv 2048
#define Cv 1024
#define HSv 64
#define Mv (Bv*Tv)           // 16384 total rows
#define SPLITS 2
#define QT 128               // query rows per attention block

typedef unsigned long long u64;

// ---------- f32x2 packed-math helpers ----------
__device__ __forceinline__ u64 pack2(float a, float b){
    u64 r; asm("mov.b64 %0, {%1, %2};" : "=l"(r) : "f"(a), "f"(b)); return r;
}
__device__ __forceinline__ void unpack2(u64 v, float &a, float &b){
    asm("mov.b64 {%0, %1}, %2;" : "=f"(a), "=f"(b) : "l"(v));
}
__device__ __forceinline__ u64 ffma2(u64 a, u64 b, u64 c){
    u64 d; asm("fma.rn.f32x2 %0, %1, %2, %3;" : "=l"(d) : "l"(a), "l"(b), "l"(c)); return d;
}
__device__ __forceinline__ u64 fmul2(u64 a, u64 b){
    u64 d; asm("mul.rn.f32x2 %0, %1, %2;" : "=l"(d) : "l"(a), "l"(b)); return d;
}

// ---------- cp.async helpers ----------
__device__ __forceinline__ void cp16(void* dst_smem, const void* src){
    unsigned d = (unsigned)__cvta_generic_to_shared(dst_smem);
    asm volatile("cp.async.cg.shared.global [%0], [%1], 16;" :: "r"(d), "l"(src));
}
__device__ __forceinline__ void cp4(void* dst_smem, const void* src){
    unsigned d = (unsigned)__cvta_generic_to_shared(dst_smem);
    asm volatile("cp.async.ca.shared.global [%0], [%1], 4;" :: "r"(d), "l"(src));
}
#define CP_COMMIT() asm volatile("cp.async.commit_group;")
#define CP_WAIT1()  asm volatile("cp.async.wait_group 1;")

// ---------- scratch ----------
__device__ float g_qkv[3*(size_t)Mv*HSv];
__device__ float g_pacc[SPLITS*(size_t)Mv*HSv];
__device__ float g_pm[SPLITS*Mv];
__device__ float g_pl[SPLITS*Mv];

// =====================================================================
// Kernel 1: projections  out[z] = X[z] @ W[z]
// 128x64 tile, K chunks of 32, cp.async double buffer, swizzled As.
// =====================================================================
__global__ __launch_bounds__(256, 3) void proj_kernel(
    const float* __restrict__ qv, const float* __restrict__ kvec,
    const float* __restrict__ vv,
    const float* __restrict__ Wq, const float* __restrict__ Wk,
    const float* __restrict__ Wv)
{
    __shared__ __align__(16) float As[2][128*32];   // xor-swizzled 16B chunks
    __shared__ __align__(16) float Ws[2][32*64];

    const int z = blockIdx.y;
    const float* A = (z==0) ? qv : (z==1) ? kvec : vv;
    const float* W = (z==0) ? Wq : (z==1) ? Wk : Wv;
    float* out = g_qkv + (size_t)z * Mv * HSv;

    const int t  = threadIdx.x;
    const int m0 = blockIdx.x * 128;
    const int tx = t & 7;          // owns cols [tx*4..tx*4+3] and [32+tx*4..]
    const int ty = t >> 3;         // owns rows ty*4 .. ty*4+3

    // ---- async load of one K-chunk into buffer `buf` ----
    auto load_chunk = [&](int kc, int buf){
        #pragma unroll
        for (int i = 0; i < 4; i++){               // As: 1024 chunks / 256 thr
            int idx = t + i*256; int r = idx >> 3, c4 = idx & 7;
            int pc = c4 ^ ((r >> 2) & 7);          // xor swizzle (bank-safe)
            cp16(&As[buf][r*32 + pc*4],
                 A + (size_t)(m0 + r)*Cv + kc*32 + c4*4);
        }
        #pragma unroll
        for (int i = 0; i < 2; i++){               // Ws: 512 chunks
            int idx = t + i*256; int r = idx >> 4, c4 = idx & 15;
            cp16(&Ws[buf][r*64 + c4*4],
                 W + (size_t)(kc*32 + r)*HSv + c4*4);
        }
    };

    load_chunk(0, 0); CP_COMMIT();
    load_chunk(1, 1); CP_COMMIT();

    u64 acc[4][4];
    const u64 z2 = pack2(0.f, 0.f);
    #pragma unroll
    for (int i = 0; i < 4; i++)
        #pragma unroll
        for (int j = 0; j < 4; j++) acc[i][j] = z2;

    const int sw = ty & 7;

    #pragma unroll 1
    for (int kc = 0; kc < Cv/32; kc++){
        CP_WAIT1();
        __syncthreads();
        const int buf = kc & 1;
        const float* AsB = As[buf];
        const float* WsB = Ws[buf];

        #pragma unroll
        for (int kk4 = 0; kk4 < 8; kk4++){
            float4 a[4];
            #pragma unroll
            for (int i = 0; i < 4; i++)
                a[i] = *(const float4*)(AsB + (ty*4 + i)*32 + ((kk4 ^ sw)*4));
            #pragma unroll
            for (int kk = 0; kk < 4; kk++){
                const float* wr = WsB + (kk4*4 + kk)*64;
                ulonglong2 wl = *(const ulonglong2*)(wr + tx*4);       // cols tx*4..+3
                ulonglong2 wh = *(const ulonglong2*)(wr + 32 + tx*4);  // cols 32+tx*4..
                #pragma unroll
                for (int i = 0; i < 4; i++){
                    float av = ((const float*)&a[i])[kk];
                    u64 ap = pack2(av, av);
                    acc[i][0] = ffma2(ap, wl.x, acc[i][0]);
                    acc[i][1] = ffma2(ap, wl.y, acc[i][1]);
                    acc[i][2] = ffma2(ap, wh.x, acc[i][2]);
                    acc[i][3] = ffma2(ap, wh.y, acc[i][3]);
                }
            }
        }
        __syncthreads();
        if (kc + 2 < Cv/32) load_chunk(kc + 2, buf);
        CP_COMMIT();
    }

    #pragma unroll
    for (int i = 0; i < 4; i++){
        float* orow = out + (size_t)(m0 + ty*4 + i)*HSv;
        ulonglong2 lo; lo.x = acc[i][0]; lo.y = acc[i][1];
        ulonglong2 hi; hi.x = acc[i][2]; hi.y = acc[i][3];
        *(ulonglong2*)(orow + tx*4)      = lo;
        *(ulonglong2*)(orow + 32 + tx*4) = hi;
    }
}

// =====================================================================
// Kernel 2: causal flash attention, balanced split-K, 2 threads/row.
// 256 threads: row = t>>1, h = t&1 (adjacent lanes -> shfl_xor 1).
// K/V tiles of 32 keys, cp.async double-buffered, 144B-offset halves.
// =====================================================================
__global__ __launch_bounds__(256, 2) void attn_kernel(const int* __restrict__ mask)
{
    const int qb = blockIdx.x;
    const int s  = blockIdx.y;
    const int b  = blockIdx.z;
    const int t  = threadIdx.x;
    const int row  = qb*QT + (t >> 1);
    const int h    = t & 1;
    const int bT   = b*Tv;
    const int rowg = bT + row;

    const int half   = (qb + 1) * 64;          // balanced: each split gets qend/2
    const int kstart = s * half;
    const int nt     = half >> 5;              // >= 2 always

    const float* Qp = g_qkv;
    const float* Kp = g_qkv + (size_t)Mv*HSv;
    const float* Vp = g_qkv + 2*(size_t)Mv*HSv;

    // rows of 72 floats: half0 at +0 (32f), half1 at +36 (32f) -> bank-safe
    __shared__ __align__(16) float Ks[2][32*72];
    __shared__ __align__(16) float Vs[2][32*72];
    __shared__ int Ms[2][32];

    auto load_tile = [&](int tile, int buf){
        int kt = kstart + tile*32;
        #pragma unroll
        for (int i = 0; i < 2; i++){            // K: 512 chunks / 256 thr
            int idx = t + i*256; int j = idx >> 4, c4 = idx & 15;
            int dst = j*72 + (c4 >> 3)*36 + (c4 & 7)*4;
            cp16(&Ks[buf][dst], Kp + (size_t)(bT + kt + j)*HSv + c4*4);
        }
        #pragma unroll
        for (int i = 0; i < 2; i++){            // V
            int idx = t + i*256; int j = idx >> 4, c4 = idx & 15;
            int dst = j*72 + (c4 >> 3)*36 + (c4 & 7)*4;
            cp16(&Vs[buf][dst], Vp + (size_t)(bT + kt + j)*HSv + c4*4);
        }
        if (t < 32) cp4(&Ms[buf][t], mask + bT + kt + t);
    };

    // my half of the query row, pre-scaled by HS^-0.5
    u64 qp[16];
    {
        const u64 sc2 = pack2(0.125f, 0.125f);
        const ulonglong2* qr = (const ulonglong2*)(Qp + (size_t)rowg*HSv + h*32);
        #pragma unroll
        for (int c = 0; c < 8; c++){
            ulonglong2 u = qr[c];
            qp[2*c]   = fmul2(u.x, sc2);
            qp[2*c+1] = fmul2(u.y, sc2);
        }
    }

    u64 acc[16];
    #pragma unroll
    for (int c = 0; c < 16; c++) acc[c] = pack2(0.f, 0.f);
    float m = -INFINITY, l = 0.f;

    load_tile(0, 0); CP_COMMIT();
    load_tile(1, 1); CP_COMMIT();

    #pragma unroll 1
    for (int tt = 0; tt < nt; tt++){
        CP_WAIT1();
        __syncthreads();
        const int buf = tt & 1;
        const float* KsB = Ks[buf];
        const float* VsB = Vs[buf];
        const int*   MsB = Ms[buf];
        const int kt0 = kstart + tt*32;
        const int lim = row - kt0;               // j valid iff j <= lim

        #pragma unroll
        for (int j0 = 0; j0 < 32; j0 += 16){     // 16-key sub-tiles (reg pressure)
            if (lim < j0) break;
            float sj[16];
            #pragma unroll
            for (int jj = 0; jj < 16; jj++){
                const int j = j0 + jj;
                const ulonglong2* kb = (const ulonglong2*)(KsB + j*72 + h*36);
                u64 a0 = pack2(0.f,0.f), a1 = pack2(0.f,0.f);
                #pragma unroll
                for (int c = 0; c < 8; c++){
                    ulonglong2 k2 = kb[c];
                    a0 = ffma2(qp[2*c],   k2.x, a0);
                    a1 = ffma2(qp[2*c+1], k2.y, a1);
                }
                float x0,x1,y0,y1;
                unpack2(a0,x0,x1); unpack2(a1,y0,y1);
                float d = (x0+y0) + (x1+y1);
                d += __shfl_xor_sync(0xFFFFFFFFu, d, 1);
                sj[jj] = (j <= lim && MsB[j]) ? d : -INFINITY;
            }
            float tm = -INFINITY;
            #pragma unroll
            for (int jj = 0; jj < 16; jj++) tm = fmaxf(tm, sj[jj]);
            float mn = fmaxf(m, tm);
            if (mn > -INFINITY){
                float corr = __expf(m - mn);
                u64 c2 = pack2(corr, corr);
                #pragma unroll
                for (int c = 0; c < 16; c++) acc[c] = fmul2(acc[c], c2);
                float ls = 0.f;
                #pragma unroll
                for (int jj = 0; jj < 16; jj++){ sj[jj] = __expf(sj[jj] - mn); ls += sj[jj]; }
                l = l*corr + ls;
                m = mn;
                #pragma unroll
                for (int jj = 0; jj < 16; jj++){
                    const int j = j0 + jj;
                    u64 pj = pack2(sj[jj], sj[jj]);
                    const ulonglong2* vb = (const ulonglong2*)(VsB + j*72 + h*36);
                    #pragma unroll
                    for (int c = 0; c < 8; c++){
                        ulonglong2 v2 = vb[c];
                        acc[2*c]   = ffma2(pj, v2.x, acc[2*c]);
                        acc[2*c+1] = ffma2(pj, v2.y, acc[2*c+1]);
                    }
                }
            }
        }
        __syncthreads();
        if (tt + 2 < nt) load_tile(tt + 2, buf);
        CP_COMMIT();
    }

    if (h == 0){
        g_pm[s*Mv + rowg] = m;
        g_pl[s*Mv + rowg] = l;
    }
    ulonglong2* pa = (ulonglong2*)(g_pacc + (size_t)(s*Mv + rowg)*HSv + h*32);
    #pragma unroll
    for (int c = 0; c < 8; c++){
        ulonglong2 u; u.x = acc[2*c]; u.y = acc[2*c+1];
        pa[c] = u;
    }
}

// =====================================================================
// Kernel 3: merge split-K partials -> final output
// =====================================================================
__global__ __launch_bounds__(256) void merge_kernel(float* __restrict__ out)
{
    int gid = blockIdx.x * blockDim.x + threadIdx.x;
    int row = gid >> 4, c4 = gid & 15;
    float m0 = g_pm[row],      m1 = g_pm[Mv + row];
    float l0 = g_pl[row],      l1 = g_pl[Mv + row];
    float M  = fmaxf(m0, m1);
    float4 o = make_float4(0.f, 0.f, 0.f, 0.f);
    if (M > -INFINITY){
        float w0 = __expf(m0 - M), w1 = __expf(m1 - M);
        float denom = l0*w0 + l1*w1;
        float inv = (denom > 0.f) ? 1.f/denom : 0.f;
        float4 a0 = ((const float4*)g_pacc)[(size_t)row*16 + c4];
        float4 a1 = ((const float4*)(g_pacc + (size_t)Mv*HSv))[(size_t)row*16 + c4];
        o.x = (a0.x*w0 + a1.x*w1)*inv;
        o.y = (a0.y*w0 + a1.y*w1)*inv;
        o.z = (a0.z*w0 + a1.z*w1)*inv;
        o.w = (a0.w*w0 + a1.w*w1)*inv;
    }
    ((float4*)out)[gid] = o;
}

// =====================================================================
extern "C" void kernel_launch(void* const* d_in, const int* in_sizes, int n_in,
                              void* d_out, int out_size)
{
    const float* q_vec = (const float*)d_in[0];
    const float* k_vec = (const float*)d_in[1];
    const float* v_vec = (const float*)d_in[2];
    const int*   mask  = (const int*)  d_in[3];
    const float* Wq    = (const float*)d_in[4];
    const float* Wk    = (const float*)d_in[5];
    const float* Wv    = (const float*)d_in[6];
    float* out = (float*)d_out;

    proj_kernel<<<dim3(Mv/128, 3), 256>>>(q_vec, k_vec, v_vec, Wq, Wk, Wv);
    attn_kernel<<<dim3(Tv/QT, SPLITS, Bv), 256>>>(mask);
    merge_kernel<<<(Mv*16)/256, 256>>>(out);
}

// round 4
// speedup vs baseline: 2.3166x; 1.4891x over previous
#include <cuda_runtime.h>
#include <math.h>

#define Bv 8
#define Tv 2048
#define Cv 1024
#define HSv 64
#define Mv (Bv*Tv)
#define QT 128
#define SLOTS 16            // max key-chunks per q-block (qb+1 <= 16)

typedef unsigned long long u64;

// ---------- f32x2 helpers ----------
__device__ __forceinline__ u64 pack2(float a, float b){
    u64 r; asm("mov.b64 %0, {%1, %2};" : "=l"(r) : "f"(a), "f"(b)); return r;
}
__device__ __forceinline__ void unpack2(u64 v, float &a, float &b){
    asm("mov.b64 {%0, %1}, %2;" : "=f"(a), "=f"(b) : "l"(v));
}
__device__ __forceinline__ u64 ffma2(u64 a, u64 b, u64 c){
    u64 d; asm("fma.rn.f32x2 %0, %1, %2, %3;" : "=l"(d) : "l"(a), "l"(b), "l"(c)); return d;
}
__device__ __forceinline__ u64 fmul2(u64 a, u64 b){
    u64 d; asm("mul.rn.f32x2 %0, %1, %2;" : "=l"(d) : "l"(a), "l"(b)); return d;
}

// ---------- cp.async ----------
__device__ __forceinline__ void cp16(void* dst_smem, const void* src){
    unsigned d = (unsigned)__cvta_generic_to_shared(dst_smem);
    asm volatile("cp.async.cg.shared.global [%0], [%1], 16;" :: "r"(d), "l"(src));
}
__device__ __forceinline__ void cp4(void* dst_smem, const void* src){
    unsigned d = (unsigned)__cvta_generic_to_shared(dst_smem);
    asm volatile("cp.async.ca.shared.global [%0], [%1], 4;" :: "r"(d), "l"(src));
}
#define CP_COMMIT() asm volatile("cp.async.commit_group;")
#define CP_WAIT1()  asm volatile("cp.async.wait_group 1;")

// ---------- scratch ----------
__device__ float g_qkv[3*(size_t)Mv*HSv];
__device__ float g_pacc[(size_t)SLOTS*Mv*HSv];   // 256 MB partials
__device__ float g_pm[SLOTS*Mv];
__device__ float g_pl[SLOTS*Mv];

// =====================================================================
// Kernel 1: projections (unchanged from R3 win)
// =====================================================================
__global__ __launch_bounds__(256, 3) void proj_kernel(
    const float* __restrict__ qv, const float* __restrict__ kvec,
    const float* __restrict__ vv,
    const float* __restrict__ Wq, const float* __restrict__ Wk,
    const float* __restrict__ Wv)
{
    __shared__ __align__(16) float As[2][128*32];
    __shared__ __align__(16) float Ws[2][32*64];

    const int z = blockIdx.y;
    const float* A = (z==0) ? qv : (z==1) ? kvec : vv;
    const float* W = (z==0) ? Wq : (z==1) ? Wk : Wv;
    float* out = g_qkv + (size_t)z * Mv * HSv;

    const int t  = threadIdx.x;
    const int m0 = blockIdx.x * 128;
    const int tx = t & 7;
    const int ty = t >> 3;

    auto load_chunk = [&](int kc, int buf){
        #pragma unroll
        for (int i = 0; i < 4; i++){
            int idx = t + i*256; int r = idx >> 3, c4 = idx & 7;
            int pc = c4 ^ ((r >> 2) & 7);
            cp16(&As[buf][r*32 + pc*4], A + (size_t)(m0 + r)*Cv + kc*32 + c4*4);
        }
        #pragma unroll
        for (int i = 0; i < 2; i++){
            int idx = t + i*256; int r = idx >> 4, c4 = idx & 15;
            cp16(&Ws[buf][r*64 + c4*4], W + (size_t)(kc*32 + r)*HSv + c4*4);
        }
    };

    load_chunk(0, 0); CP_COMMIT();
    load_chunk(1, 1); CP_COMMIT();

    u64 acc[4][4];
    const u64 z2 = pack2(0.f, 0.f);
    #pragma unroll
    for (int i = 0; i < 4; i++)
        #pragma unroll
        for (int j = 0; j < 4; j++) acc[i][j] = z2;

    const int sw = ty & 7;

    #pragma unroll 1
    for (int kc = 0; kc < Cv/32; kc++){
        CP_WAIT1();
        __syncthreads();
        const int buf = kc & 1;
        const float* AsB = As[buf];
        const float* WsB = Ws[buf];

        #pragma unroll
        for (int kk4 = 0; kk4 < 8; kk4++){
            float4 a[4];
            #pragma unroll
            for (int i = 0; i < 4; i++)
                a[i] = *(const float4*)(AsB + (ty*4 + i)*32 + ((kk4 ^ sw)*4));
            #pragma unroll
            for (int kk = 0; kk < 4; kk++){
                const float* wr = WsB + (kk4*4 + kk)*64;
                ulonglong2 wl = *(const ulonglong2*)(wr + tx*4);
                ulonglong2 wh = *(const ulonglong2*)(wr + 32 + tx*4);
                #pragma unroll
                for (int i = 0; i < 4; i++){
                    float av = ((const float*)&a[i])[kk];
                    u64 ap = pack2(av, av);
                    acc[i][0] = ffma2(ap, wl.x, acc[i][0]);
                    acc[i][1] = ffma2(ap, wl.y, acc[i][1]);
                    acc[i][2] = ffma2(ap, wh.x, acc[i][2]);
                    acc[i][3] = ffma2(ap, wh.y, acc[i][3]);
                }
            }
        }
        __syncthreads();
        if (kc + 2 < Cv/32) load_chunk(kc + 2, buf);
        CP_COMMIT();
    }

    #pragma unroll
    for (int i = 0; i < 4; i++){
        float* orow = out + (size_t)(m0 + ty*4 + i)*HSv;
        ulonglong2 lo; lo.x = acc[i][0]; lo.y = acc[i][1];
        ulonglong2 hi; hi.x = acc[i][2]; hi.y = acc[i][3];
        *(ulonglong2*)(orow + tx*4)      = lo;
        *(ulonglong2*)(orow + 32 + tx*4) = hi;
    }
}

// =====================================================================
// Kernel 2: attention as two register-tiled GEMMs, uniform 128-key chunks.
// Grid: x = triangular (qb, s) with s<=qb (136), y = batch (8).
// Block: 256 thr as 32x8: thread owns 4 rows (ty*4..) x {4 keys | 8 cols}.
// =====================================================================
// dynamic smem layout (floats):
#define SM_QS   0                      // 128*68
#define SM_KS   (128*68)               // 2*32*64
#define SM_VS   (SM_KS + 2*32*64)      // 2*32*64
#define SM_PS   (SM_VS + 2*32*64)      // 128*36
#define SM_M    (SM_PS + 128*36)       // 128
#define SM_L    (SM_M + 128)           // 128
#define SM_C    (SM_L + 128)           // 128
#define SM_MSK  (SM_C + 128)           // 64 ints
#define SMEM_ATTN_BYTES ((SM_MSK + 64)*4)

__global__ __launch_bounds__(256, 2) void attn_kernel(const int* __restrict__ mask)
{
    extern __shared__ __align__(16) float sm[];
    float* Qs  = sm + SM_QS;
    float* Ks  = sm + SM_KS;
    float* Vs  = sm + SM_VS;
    float* Ps  = sm + SM_PS;
    float* Msm = sm + SM_M;
    float* Lsm = sm + SM_L;
    float* Csm = sm + SM_C;
    int*   Msk = (int*)(sm + SM_MSK);

    // decode triangular (qb, s)
    int x = blockIdx.x;
    int qb = (int)((sqrtf(8.f*x + 1.f) - 1.f) * 0.5f);
    while ((qb+1)*(qb+2)/2 <= x) qb++;
    while (qb*(qb+1)/2 > x) qb--;
    const int s = x - qb*(qb+1)/2;        // key chunk index, 0..qb

    const int b    = blockIdx.y;
    const int t    = threadIdx.x;
    const int tx   = t & 7;
    const int ty   = t >> 3;
    const int bT   = b*Tv;
    const int row0 = qb*QT;
    const int kstart = s*128;
    const int nt = 4;                     // 4 tiles of 32 keys

    const float* Qp = g_qkv;
    const float* Kp = g_qkv + (size_t)Mv*HSv;
    const float* Vp = g_qkv + 2*(size_t)Mv*HSv;

    if (t < 128){ Msm[t] = -INFINITY; Lsm[t] = 0.f; }

    // Q tile: 128x64 -> Qs stride 68 (2048 16B-chunks)
    #pragma unroll
    for (int i = 0; i < 8; i++){
        int idx = t + i*256; int r = idx >> 4, c4 = idx & 15;
        cp16(&Qs[r*68 + c4*4], Qp + (size_t)(bT + row0 + r)*HSv + c4*4);
    }

    auto load_tile = [&](int tile, int buf){
        int kt = kstart + tile*32;
        #pragma unroll
        for (int i = 0; i < 2; i++){      // K with per-row-quad xor swizzle
            int idx = t + i*256; int r = idx >> 4, c4 = idx & 15;
            int pc = c4 ^ ((r >> 2) & 7);
            cp16(&Ks[buf*2048 + r*64 + pc*4], Kp + (size_t)(bT + kt + r)*HSv + c4*4);
        }
        #pragma unroll
        for (int i = 0; i < 2; i++){      // V straight
            int idx = t + i*256; int r = idx >> 4, c4 = idx & 15;
            cp16(&Vs[buf*2048 + r*64 + c4*4], Vp + (size_t)(bT + kt + r)*HSv + c4*4);
        }
        if (t < 32) cp4(&Msk[buf*32 + t], mask + bT + kt + t);
    };

    load_tile(0, 0); CP_COMMIT();         // group includes Q
    load_tile(1, 1); CP_COMMIT();

    u64 oacc[16];
    const u64 z2 = pack2(0.f, 0.f);
    #pragma unroll
    for (int c = 0; c < 16; c++) oacc[c] = z2;

    #pragma unroll 1
    for (int tt = 0; tt < nt; tt++){
        CP_WAIT1();
        __syncthreads();
        const int buf = tt & 1;
        const float* KsB = Ks + buf*2048;
        const float* VsB = Vs + buf*2048;
        const int kt0 = kstart + tt*32;

        // ---- GEMM1: S[4 rows][4 keys] = Q . K^T (f32x2 over h) ----
        u64 sa[16];
        #pragma unroll
        for (int c = 0; c < 16; c++) sa[c] = z2;
        #pragma unroll
        for (int h4 = 0; h4 < 16; h4++){
            ulonglong2 qv[4], kv[4];
            #pragma unroll
            for (int i = 0; i < 4; i++)
                qv[i] = *(const ulonglong2*)(Qs + (ty*4 + i)*68 + h4*4);
            #pragma unroll
            for (int j = 0; j < 4; j++)
                kv[j] = *(const ulonglong2*)(KsB + (tx*4 + j)*64 + ((h4 ^ tx)*4));
            #pragma unroll
            for (int i = 0; i < 4; i++)
                #pragma unroll
                for (int j = 0; j < 4; j++){
                    sa[i*4+j] = ffma2(qv[i].x, kv[j].x, sa[i*4+j]);
                    sa[i*4+j] = ffma2(qv[i].y, kv[j].y, sa[i*4+j]);
                }
        }

        // ---- reduce, scale, mask ----
        float s_[16];
        int mk[4];
        #pragma unroll
        for (int j = 0; j < 4; j++) mk[j] = Msk[buf*32 + tx*4 + j];
        #pragma unroll
        for (int i = 0; i < 4; i++){
            int r = row0 + ty*4 + i;
            #pragma unroll
            for (int j = 0; j < 4; j++){
                float a, b2; unpack2(sa[i*4+j], a, b2);
                float sv = (a + b2) * 0.125f;
                int kg = kt0 + tx*4 + j;
                s_[i*4+j] = (kg <= r && mk[j]) ? sv : -INFINITY;
            }
        }

        // ---- softmax (stats per row in smem) ----
        float tmax[4], mold[4], mnew[4], psum[4];
        #pragma unroll
        for (int i = 0; i < 4; i++){
            float tm = fmaxf(fmaxf(s_[i*4],s_[i*4+1]), fmaxf(s_[i*4+2],s_[i*4+3]));
            tm = fmaxf(tm, __shfl_xor_sync(0xFFFFFFFFu, tm, 1));
            tm = fmaxf(tm, __shfl_xor_sync(0xFFFFFFFFu, tm, 2));
            tm = fmaxf(tm, __shfl_xor_sync(0xFFFFFFFFu, tm, 4));
            tmax[i] = tm;
        }
        #pragma unroll
        for (int i = 0; i < 4; i++){
            mold[i] = Msm[ty*4 + i];
            mnew[i] = fmaxf(fmaxf(mold[i], tmax[i]), -1e30f);
        }
        #pragma unroll
        for (int i = 0; i < 4; i++){
            float ps = 0.f;
            #pragma unroll
            for (int j = 0; j < 4; j++){
                float p = __expf(s_[i*4+j] - mnew[i]);
                s_[i*4+j] = p; ps += p;
            }
            ps += __shfl_xor_sync(0xFFFFFFFFu, ps, 1);
            ps += __shfl_xor_sync(0xFFFFFFFFu, ps, 2);
            ps += __shfl_xor_sync(0xFFFFFFFFu, ps, 4);
            psum[i] = ps;
        }
        if (tx == 0){
            #pragma unroll
            for (int i = 0; i < 4; i++){
                float corr = __expf(mold[i] - mnew[i]);
                Csm[ty*4+i] = corr;
                Lsm[ty*4+i] = Lsm[ty*4+i]*corr + psum[i];
                Msm[ty*4+i] = mnew[i];
            }
        }
        #pragma unroll
        for (int i = 0; i < 4; i++)
            *(float4*)(Ps + (ty*4+i)*36 + tx*4) =
                make_float4(s_[i*4], s_[i*4+1], s_[i*4+2], s_[i*4+3]);
        __syncthreads();

        // ---- GEMM2: O[4 rows][8 cols] += P . V ----
        #pragma unroll
        for (int i = 0; i < 4; i++){
            float c = Csm[ty*4 + i];
            u64 cc = pack2(c, c);
            #pragma unroll
            for (int cx = 0; cx < 4; cx++) oacc[i*4+cx] = fmul2(oacc[i*4+cx], cc);
        }
        #pragma unroll 8
        for (int kk = 0; kk < 32; kk++){
            ulonglong2 v0 = *(const ulonglong2*)(VsB + kk*64 + tx*8);
            ulonglong2 v1 = *(const ulonglong2*)(VsB + kk*64 + tx*8 + 4);
            #pragma unroll
            for (int i = 0; i < 4; i++){
                float p = Ps[(ty*4+i)*36 + kk];
                u64 pp = pack2(p, p);
                oacc[i*4+0] = ffma2(pp, v0.x, oacc[i*4+0]);
                oacc[i*4+1] = ffma2(pp, v0.y, oacc[i*4+1]);
                oacc[i*4+2] = ffma2(pp, v1.x, oacc[i*4+2]);
                oacc[i*4+3] = ffma2(pp, v1.y, oacc[i*4+3]);
            }
        }
        __syncthreads();
        if (tt + 2 < nt) load_tile(tt + 2, buf);
        CP_COMMIT();
    }

    // ---- write partials (slot s) ----
    if (t < 128){
        g_pm[s*Mv + bT + row0 + t] = Msm[t];
        g_pl[s*Mv + bT + row0 + t] = Lsm[t];
    }
    #pragma unroll
    for (int i = 0; i < 4; i++){
        float* pa = g_pacc + ((size_t)s*Mv + bT + row0 + ty*4 + i)*HSv + tx*8;
        ulonglong2 u0; u0.x = oacc[i*4+0]; u0.y = oacc[i*4+1];
        ulonglong2 u1; u1.x = oacc[i*4+2]; u1.y = oacc[i*4+3];
        *(ulonglong2*)pa = u0;
        *(ulonglong2*)(pa + 4) = u1;
    }
}

// =====================================================================
// Kernel 3: merge variable-count partials
// =====================================================================
__global__ __launch_bounds__(256) void merge_kernel(float* __restrict__ out)
{
    int gid = blockIdx.x * blockDim.x + threadIdx.x;
    int row = gid >> 4, c4 = gid & 15;
    const int ns = ((row & (Tv-1)) >> 7) + 1;    // qb+1 chunks

    float M = -INFINITY;
    for (int s2 = 0; s2 < ns; s2++) M = fmaxf(M, g_pm[s2*Mv + row]);

    float4 o = make_float4(0.f, 0.f, 0.f, 0.f);
    float denom = 0.f;
    if (M > -INFINITY){
        for (int s2 = 0; s2 < ns; s2++){
            float w = __expf(g_pm[s2*Mv + row] - M);
            denom += g_pl[s2*Mv + row] * w;
            float4 a = ((const float4*)g_pacc)[((size_t)s2*Mv + row)*16 + c4];
            o.x += a.x*w; o.y += a.y*w; o.z += a.z*w; o.w += a.w*w;
        }
        float inv = (denom > 0.f) ? 1.f/denom : 0.f;
        o.x *= inv; o.y *= inv; o.z *= inv; o.w *= inv;
    }
    ((float4*)out)[gid] = o;
}

// =====================================================================
extern "C" void kernel_launch(void* const* d_in, const int* in_sizes, int n_in,
                              void* d_out, int out_size)
{
    const float* q_vec = (const float*)d_in[0];
    const float* k_vec = (const float*)d_in[1];
    const float* v_vec = (const float*)d_in[2];
    const int*   mask  = (const int*)  d_in[3];
    const float* Wq    = (const float*)d_in[4];
    const float* Wk    = (const float*)d_in[5];
    const float* Wv    = (const float*)d_in[6];
    float* out = (float*)d_out;

    cudaFuncSetAttribute(attn_kernel,
        cudaFuncAttributeMaxDynamicSharedMemorySize, SMEM_ATTN_BYTES);

    proj_kernel<<<dim3(Mv/128, 3), 256>>>(q_vec, k_vec, v_vec, Wq, Wk, Wv);
    attn_kernel<<<dim3((Tv/QT)*(Tv/QT + 1)/2, Bv), 256, SMEM_ATTN_BYTES>>>(mask);
    merge_kernel<<<(Mv*16)/256, 256>>>(out);
}

// round 6
// speedup vs baseline: 2.9057x; 1.2543x over previous
#include <cuda_runtime.h>
#include <cuda_bf16.h>
#include <math.h>

#define Bv 8
#define Tv 2048
#define Cv 1024
#define HSv 64
#define Mv (Bv*Tv)
#define QT 128
#define SLOTS 16

typedef unsigned long long u64;
typedef unsigned int u32;

// ---------- f32x2 helpers ----------
__device__ __forceinline__ u64 pack2(float a, float b){
    u64 r; asm("mov.b64 %0, {%1, %2};" : "=l"(r) : "f"(a), "f"(b)); return r;
}
__device__ __forceinline__ void unpack2(u64 v, float &a, float &b){
    asm("mov.b64 {%0, %1}, %2;" : "=f"(a), "=f"(b) : "l"(v));
}
__device__ __forceinline__ u64 ffma2(u64 a, u64 b, u64 c){
    u64 d; asm("fma.rn.f32x2 %0, %1, %2, %3;" : "=l"(d) : "l"(a), "l"(b), "l"(c)); return d;
}
__device__ __forceinline__ u64 fmul2(u64 a, u64 b){
    u64 d; asm("mul.rn.f32x2 %0, %1, %2;" : "=l"(d) : "l"(a), "l"(b)); return d;
}

// ---------- cp.async ----------
__device__ __forceinline__ void cp16(void* dst_smem, const void* src){
    unsigned d = (unsigned)__cvta_generic_to_shared(dst_smem);
    asm volatile("cp.async.cg.shared.global [%0], [%1], 16;" :: "r"(d), "l"(src));
}
__device__ __forceinline__ void cp4(void* dst_smem, const void* src){
    unsigned d = (unsigned)__cvta_generic_to_shared(dst_smem);
    asm volatile("cp.async.ca.shared.global [%0], [%1], 4;" :: "r"(d), "l"(src));
}
#define CP_COMMIT() asm volatile("cp.async.commit_group;")
#define CP_WAIT1()  asm volatile("cp.async.wait_group 1;")

// ---------- mma.sync helpers (portable, sm_80+) ----------
__device__ __forceinline__ u32 smem_u32(const void* p){
    return (u32)__cvta_generic_to_shared(p);
}
__device__ __forceinline__ void ldsm_x4(u32 &r0,u32 &r1,u32 &r2,u32 &r3, u32 addr){
    asm volatile("ldmatrix.sync.aligned.m8n8.x4.shared.b16 {%0,%1,%2,%3}, [%4];"
        : "=r"(r0),"=r"(r1),"=r"(r2),"=r"(r3) : "r"(addr));
}
__device__ __forceinline__ void ldsm_x2(u32 &r0,u32 &r1, u32 addr){
    asm volatile("ldmatrix.sync.aligned.m8n8.x2.shared.b16 {%0,%1}, [%2];"
        : "=r"(r0),"=r"(r1) : "r"(addr));
}
__device__ __forceinline__ void mma16816(float* d, const u32* a, const u32* b){
    asm volatile("mma.sync.aligned.m16n8k16.row.col.f32.bf16.bf16.f32 "
        "{%0,%1,%2,%3}, {%4,%5,%6,%7}, {%8,%9}, {%0,%1,%2,%3};"
        : "+f"(d[0]),"+f"(d[1]),"+f"(d[2]),"+f"(d[3])
        : "r"(a[0]),"r"(a[1]),"r"(a[2]),"r"(a[3]), "r"(b[0]),"r"(b[1]));
}

// ---------- scratch ----------
__device__ float g_qkv[3*(size_t)Mv*HSv];
__device__ float g_pacc[(size_t)SLOTS*Mv*HSv];
__device__ float g_pm[SLOTS*Mv];
__device__ float g_pl[SLOTS*Mv];
__device__ __nv_bfloat16 g_wt[3*2*64*1024];   // [z][hi/lo][n][k]

// =====================================================================
// Kernel 0: transpose + bf16-split weights:  g_wt[z][hl][n][k]
// =====================================================================
__global__ __launch_bounds__(256) void prep_wt(
    const float* __restrict__ Wq, const float* __restrict__ Wk,
    const float* __restrict__ Wv)
{
    int id = blockIdx.x*256 + threadIdx.x;        // 3*64*1024
    int z = id >> 16; int rem = id & 65535;
    int n = rem >> 10; int k = rem & 1023;
    const float* W = (z==0) ? Wq : (z==1) ? Wk : Wv;
    float w = W[k*64 + n];
    __nv_bfloat16 h = __float2bfloat16(w);
    float r = w - __bfloat162float(h);
    g_wt[(size_t)(z*2+0)*65536 + n*1024 + k] = h;
    g_wt[(size_t)(z*2+1)*65536 + n*1024 + k] = __float2bfloat16(r);
}

// =====================================================================
// Kernel 1: HMMA split-bf16 projection (mma.sync m16n8k16).
// CTA 128x64, 8 warps as 4(M)x2(N) -> warp tile 32x32.
// K in 16 chunks of 64. A: LDG->split->STS double buffer.
// B: cp.async 4-slot ring from prepped W^T hi/lo.
// =====================================================================
#define KCH 64
#define NCHUNK (Cv/KCH)     // 16
// smem byte offsets (rows padded to 144B = 72 bf16)
#define A_HI 0                              // + buf*18432   (2 bufs, 128 rows)
#define A_LO 36864                          // + buf*18432
#define B_HI 73728                          // + slot*9216   (4 slots, 64 rows)
#define B_LO 110592                         // + slot*9216
#define PROJ_SMEM 147456

__device__ __forceinline__ void cvt_split4(float4 a, uint2 &hi, uint2 &lo){
    __nv_bfloat162 h01 = __floats2bfloat162_rn(a.x, a.y);
    __nv_bfloat162 h23 = __floats2bfloat162_rn(a.z, a.w);
    float2 f01 = __bfloat1622float2(h01);
    float2 f23 = __bfloat1622float2(h23);
    __nv_bfloat162 l01 = __floats2bfloat162_rn(a.x - f01.x, a.y - f01.y);
    __nv_bfloat162 l23 = __floats2bfloat162_rn(a.z - f23.x, a.w - f23.y);
    hi.x = *(u32*)&h01; hi.y = *(u32*)&h23;
    lo.x = *(u32*)&l01; lo.y = *(u32*)&l23;
}

__global__ __launch_bounds__(256) void proj_mma(
    const float* __restrict__ qv, const float* __restrict__ kvec,
    const float* __restrict__ vv)
{
    extern __shared__ __align__(128) char smc[];
    const int t   = threadIdx.x;
    const int wid = t >> 5;
    const int l   = t & 31;
    const int z   = blockIdx.y;
    const int m0  = blockIdx.x * 128;
    const float* A = (z==0) ? qv : (z==1) ? kvec : vv;
    float* out = g_qkv + (size_t)z * Mv * HSv;

    const u32 sbase = smem_u32(smc);
    const int wm = wid >> 1;        // 0..3  (M)
    const int wn = wid & 1;         // 0..1  (N)

    // ldmatrix lane geometry
    const int arow  = (l & 15);            // A: row within 16-row tile
    const int acol8 = (l >> 4) * 8;        // A: +8 col for upper half-lanes
    const int brow  = (l & 7);             // B: n within 8-row tile
    const int bk8   = ((l >> 3) & 1) * 8;  // B: +8 k for lanes 8-15

    auto loadB = [&](int it2){
        int slot = it2 & 3; int k0 = it2 * KCH;
        #pragma unroll
        for (int i = 0; i < 4; i++){
            int idx = t + i*256;              // 0..1023
            int term = idx >> 9;              // 0:hi 1:lo
            int rem = idx & 511;
            int n = rem >> 3, c = rem & 7;
            cp16(smc + (term ? B_LO : B_HI) + slot*9216 + n*144 + c*16,
                 g_wt + (size_t)(z*2+term)*65536 + n*1024 + k0 + c*8);
        }
    };

    float4 aPre[8];
    auto loadA = [&](int it2){
        int k0 = it2 * KCH;
        #pragma unroll
        for (int i = 0; i < 8; i++){
            int idx = t + i*256; int r = idx >> 4, c4 = idx & 15;
            aPre[i] = *(const float4*)(A + (size_t)(m0 + r)*Cv + k0 + c4*4);
        }
    };

    loadA(0);
    loadB(0); CP_COMMIT();
    loadB(1); CP_COMMIT();

    float D[2][4][4];
    #pragma unroll
    for (int mt = 0; mt < 2; mt++)
        #pragma unroll
        for (int nc = 0; nc < 4; nc++)
            #pragma unroll
            for (int e = 0; e < 4; e++) D[mt][nc][e] = 0.f;

    #pragma unroll 1
    for (int it = 0; it < NCHUNK; it++){
        CP_WAIT1();                         // B(it) resident
        const int buf = it & 1;
        const int slot = it & 3;

        // convert + STS A(it)
        #pragma unroll
        for (int i = 0; i < 8; i++){
            int idx = t + i*256; int r = idx >> 4, c4 = idx & 15;
            uint2 hi, lo; cvt_split4(aPre[i], hi, lo);
            *(uint2*)(smc + A_HI + buf*18432 + r*144 + c4*8) = hi;
            *(uint2*)(smc + A_LO + buf*18432 + r*144 + c4*8) = lo;
        }
        __syncthreads();

        if (it + 1 < NCHUNK) loadA(it + 1);
        if (it + 2 < NCHUNK){ loadB(it + 2); CP_COMMIT(); }

        const u32 aHiB = sbase + A_HI + buf*18432;
        const u32 aLoB = sbase + A_LO + buf*18432;
        const u32 bHiB = sbase + B_HI + slot*9216;
        const u32 bLoB = sbase + B_LO + slot*9216;

        #pragma unroll
        for (int ks = 0; ks < 4; ks++){
            u32 AH[2][4], AL[2][4], BH[4][2], BL[4][2];
            #pragma unroll
            for (int mt = 0; mt < 2; mt++){
                u32 ao = (u32)((wm*32 + mt*16 + arow)*144 + (ks*16 + acol8)*2);
                ldsm_x4(AH[mt][0], AH[mt][1], AH[mt][2], AH[mt][3], aHiB + ao);
                ldsm_x4(AL[mt][0], AL[mt][1], AL[mt][2], AL[mt][3], aLoB + ao);
            }
            #pragma unroll
            for (int nc = 0; nc < 4; nc++){
                u32 bo = (u32)((wn*32 + nc*8 + brow)*144 + (ks*16 + bk8)*2);
                ldsm_x2(BH[nc][0], BH[nc][1], bHiB + bo);
                ldsm_x2(BL[nc][0], BL[nc][1], bLoB + bo);
            }
            #pragma unroll
            for (int mt = 0; mt < 2; mt++)
                #pragma unroll
                for (int nc = 0; nc < 4; nc++){
                    mma16816(D[mt][nc], AH[mt], BH[nc]);
                    mma16816(D[mt][nc], AH[mt], BL[nc]);
                    mma16816(D[mt][nc], AL[mt], BH[nc]);
                }
        }
        __syncthreads();     // all reads of A buf / B slot done before reuse
    }

    // store D: c0,c1 at (row l/4, col (l%4)*2), c2,c3 at row+8
    #pragma unroll
    for (int mt = 0; mt < 2; mt++){
        int row = m0 + wm*32 + mt*16 + (l >> 2);
        #pragma unroll
        for (int nc = 0; nc < 4; nc++){
            int col = wn*32 + nc*8 + (l & 3)*2;
            *(float2*)(out + (size_t)row*HSv + col)       = make_float2(D[mt][nc][0], D[mt][nc][1]);
            *(float2*)(out + (size_t)(row+8)*HSv + col)   = make_float2(D[mt][nc][2], D[mt][nc][3]);
        }
    }
}

// =====================================================================
// Kernel 2: attention (unchanged R4 winner)
// =====================================================================
#define SM_QS   0
#define SM_KS   (128*68)
#define SM_VS   (SM_KS + 2*32*64)
#define SM_PS   (SM_VS + 2*32*64)
#define SM_M    (SM_PS + 128*36)
#define SM_L    (SM_M + 128)
#define SM_C    (SM_L + 128)
#define SM_MSK  (SM_C + 128)
#define SMEM_ATTN_BYTES ((SM_MSK + 64)*4)

__global__ __launch_bounds__(256, 2) void attn_kernel(const int* __restrict__ mask)
{
    extern __shared__ __align__(16) float sm[];
    float* Qs  = sm + SM_QS;
    float* Ks  = sm + SM_KS;
    float* Vs  = sm + SM_VS;
    float* Ps  = sm + SM_PS;
    float* Msm = sm + SM_M;
    float* Lsm = sm + SM_L;
    float* Csm = sm + SM_C;
    int*   Msk = (int*)(sm + SM_MSK);

    int x = blockIdx.x;
    int qb = (int)((sqrtf(8.f*x + 1.f) - 1.f) * 0.5f);
    while ((qb+1)*(qb+2)/2 <= x) qb++;
    while (qb*(qb+1)/2 > x) qb--;
    const int s = x - qb*(qb+1)/2;

    const int b    = blockIdx.y;
    const int t    = threadIdx.x;
    const int tx   = t & 7;
    const int ty   = t >> 3;
    const int bT   = b*Tv;
    const int row0 = qb*QT;
    const int kstart = s*128;
    const int nt = 4;

    const float* Qp = g_qkv;
    const float* Kp = g_qkv + (size_t)Mv*HSv;
    const float* Vp = g_qkv + 2*(size_t)Mv*HSv;

    if (t < 128){ Msm[t] = -INFINITY; Lsm[t] = 0.f; }

    #pragma unroll
    for (int i = 0; i < 8; i++){
        int idx = t + i*256; int r = idx >> 4, c4 = idx & 15;
        cp16(&Qs[r*68 + c4*4], Qp + (size_t)(bT + row0 + r)*HSv + c4*4);
    }

    auto load_tile = [&](int tile, int buf){
        int kt = kstart + tile*32;
        #pragma unroll
        for (int i = 0; i < 2; i++){
            int idx = t + i*256; int r = idx >> 4, c4 = idx & 15;
            int pc = c4 ^ ((r >> 2) & 7);
            cp16(&Ks[buf*2048 + r*64 + pc*4], Kp + (size_t)(bT + kt + r)*HSv + c4*4);
        }
        #pragma unroll
        for (int i = 0; i < 2; i++){
            int idx = t + i*256; int r = idx >> 4, c4 = idx & 15;
            cp16(&Vs[buf*2048 + r*64 + c4*4], Vp + (size_t)(bT + kt + r)*HSv + c4*4);
        }
        if (t < 32) cp4(&Msk[buf*32 + t], mask + bT + kt + t);
    };

    load_tile(0, 0); CP_COMMIT();
    load_tile(1, 1); CP_COMMIT();

    u64 oacc[16];
    const u64 z2 = pack2(0.f, 0.f);
    #pragma unroll
    for (int c = 0; c < 16; c++) oacc[c] = z2;

    #pragma unroll 1
    for (int tt = 0; tt < nt; tt++){
        CP_WAIT1();
        __syncthreads();
        const int buf = tt & 1;
        const float* KsB = Ks + buf*2048;
        const float* VsB = Vs + buf*2048;
        const int kt0 = kstart + tt*32;

        u64 sa[16];
        #pragma unroll
        for (int c = 0; c < 16; c++) sa[c] = z2;
        #pragma unroll
        for (int h4 = 0; h4 < 16; h4++){
            ulonglong2 qv[4], kv[4];
            #pragma unroll
            for (int i = 0; i < 4; i++)
                qv[i] = *(const ulonglong2*)(Qs + (ty*4 + i)*68 + h4*4);
            #pragma unroll
            for (int j = 0; j < 4; j++)
                kv[j] = *(const ulonglong2*)(KsB + (tx*4 + j)*64 + ((h4 ^ tx)*4));
            #pragma unroll
            for (int i = 0; i < 4; i++)
                #pragma unroll
                for (int j = 0; j < 4; j++){
                    sa[i*4+j] = ffma2(qv[i].x, kv[j].x, sa[i*4+j]);
                    sa[i*4+j] = ffma2(qv[i].y, kv[j].y, sa[i*4+j]);
                }
        }

        float s_[16];
        int mk[4];
        #pragma unroll
        for (int j = 0; j < 4; j++) mk[j] = Msk[buf*32 + tx*4 + j];
        #pragma unroll
        for (int i = 0; i < 4; i++){
            int r = row0 + ty*4 + i;
            #pragma unroll
            for (int j = 0; j < 4; j++){
                float a, b2; unpack2(sa[i*4+j], a, b2);
                float sv = (a + b2) * 0.125f;
                int kg = kt0 + tx*4 + j;
                s_[i*4+j] = (kg <= r && mk[j]) ? sv : -INFINITY;
            }
        }

        float tmax[4], mold[4], mnew[4], psum[4];
        #pragma unroll
        for (int i = 0; i < 4; i++){
            float tmx = fmaxf(fmaxf(s_[i*4],s_[i*4+1]), fmaxf(s_[i*4+2],s_[i*4+3]));
            tmx = fmaxf(tmx, __shfl_xor_sync(0xFFFFFFFFu, tmx, 1));
            tmx = fmaxf(tmx, __shfl_xor_sync(0xFFFFFFFFu, tmx, 2));
            tmx = fmaxf(tmx, __shfl_xor_sync(0xFFFFFFFFu, tmx, 4));
            tmax[i] = tmx;
        }
        #pragma unroll
        for (int i = 0; i < 4; i++){
            mold[i] = Msm[ty*4 + i];
            mnew[i] = fmaxf(fmaxf(mold[i], tmax[i]), -1e30f);
        }
        #pragma unroll
        for (int i = 0; i < 4; i++){
            float ps = 0.f;
            #pragma unroll
            for (int j = 0; j < 4; j++){
                float p = __expf(s_[i*4+j] - mnew[i]);
                s_[i*4+j] = p; ps += p;
            }
            ps += __shfl_xor_sync(0xFFFFFFFFu, ps, 1);
            ps += __shfl_xor_sync(0xFFFFFFFFu, ps, 2);
            ps += __shfl_xor_sync(0xFFFFFFFFu, ps, 4);
            psum[i] = ps;
        }
        if (tx == 0){
            #pragma unroll
            for (int i = 0; i < 4; i++){
                float corr = __expf(mold[i] - mnew[i]);
                Csm[ty*4+i] = corr;
                Lsm[ty*4+i] = Lsm[ty*4+i]*corr + psum[i];
                Msm[ty*4+i] = mnew[i];
            }
        }
        #pragma unroll
        for (int i = 0; i < 4; i++)
            *(float4*)(Ps + (ty*4+i)*36 + tx*4) =
                make_float4(s_[i*4], s_[i*4+1], s_[i*4+2], s_[i*4+3]);
        __syncthreads();

        #pragma unroll
        for (int i = 0; i < 4; i++){
            float c = Csm[ty*4 + i];
            u64 cc = pack2(c, c);
            #pragma unroll
            for (int cx = 0; cx < 4; cx++) oacc[i*4+cx] = fmul2(oacc[i*4+cx], cc);
        }
        #pragma unroll 8
        for (int kk = 0; kk < 32; kk++){
            ulonglong2 v0 = *(const ulonglong2*)(VsB + kk*64 + tx*8);
            ulonglong2 v1 = *(const ulonglong2*)(VsB + kk*64 + tx*8 + 4);
            #pragma unroll
            for (int i = 0; i < 4; i++){
                float p = Ps[(ty*4+i)*36 + kk];
                u64 pp = pack2(p, p);
                oacc[i*4+0] = ffma2(pp, v0.x, oacc[i*4+0]);
                oacc[i*4+1] = ffma2(pp, v0.y, oacc[i*4+1]);
                oacc[i*4+2] = ffma2(pp, v1.x, oacc[i*4+2]);
                oacc[i*4+3] = ffma2(pp, v1.y, oacc[i*4+3]);
            }
        }
        __syncthreads();
        if (tt + 2 < nt) load_tile(tt + 2, buf);
        CP_COMMIT();
    }

    if (t < 128){
        g_pm[s*Mv + bT + row0 + t] = Msm[t];
        g_pl[s*Mv + bT + row0 + t] = Lsm[t];
    }
    #pragma unroll
    for (int i = 0; i < 4; i++){
        float* pa = g_pacc + ((size_t)s*Mv + bT + row0 + ty*4 + i)*HSv + tx*8;
        ulonglong2 u0; u0.x = oacc[i*4+0]; u0.y = oacc[i*4+1];
        ulonglong2 u1; u1.x = oacc[i*4+2]; u1.y = oacc[i*4+3];
        *(ulonglong2*)pa = u0;
        *(ulonglong2*)(pa + 4) = u1;
    }
}

// =====================================================================
// Kernel 3: merge (unchanged)
// =====================================================================
__global__ __launch_bounds__(256) void merge_kernel(float* __restrict__ out)
{
    int gid = blockIdx.x * blockDim.x + threadIdx.x;
    int row = gid >> 4, c4 = gid & 15;
    const int ns = ((row & (Tv-1)) >> 7) + 1;

    float M = -INFINITY;
    for (int s2 = 0; s2 < ns; s2++) M = fmaxf(M, g_pm[s2*Mv + row]);

    float4 o = make_float4(0.f, 0.f, 0.f, 0.f);
    float denom = 0.f;
    if (M > -INFINITY){
        for (int s2 = 0; s2 < ns; s2++){
            float w = __expf(g_pm[s2*Mv + row] - M);
            denom += g_pl[s2*Mv + row] * w;
            float4 a = ((const float4*)g_pacc)[((size_t)s2*Mv + row)*16 + c4];
            o.x += a.x*w; o.y += a.y*w; o.z += a.z*w; o.w += a.w*w;
        }
        float inv = (denom > 0.f) ? 1.f/denom : 0.f;
        o.x *= inv; o.y *= inv; o.z *= inv; o.w *= inv;
    }
    ((float4*)out)[gid] = o;
}

// =====================================================================
extern "C" void kernel_launch(void* const* d_in, const int* in_sizes, int n_in,
                              void* d_out, int out_size)
{
    const float* q_vec = (const float*)d_in[0];
    const float* k_vec = (const float*)d_in[1];
    const float* v_vec = (const float*)d_in[2];
    const int*   mask  = (const int*)  d_in[3];
    const float* Wq    = (const float*)d_in[4];
    const float* Wk    = (const float*)d_in[5];
    const float* Wv    = (const float*)d_in[6];
    float* out = (float*)d_out;

    cudaFuncSetAttribute(proj_mma,
        cudaFuncAttributeMaxDynamicSharedMemorySize, PROJ_SMEM);
    cudaFuncSetAttribute(attn_kernel,
        cudaFuncAttributeMaxDynamicSharedMemorySize, SMEM_ATTN_BYTES);

    prep_wt<<<768, 256>>>(Wq, Wk, Wv);
    proj_mma<<<dim3(Mv/128, 3), 256, PROJ_SMEM>>>(q_vec, k_vec, v_vec);
    attn_kernel<<<dim3((Tv/QT)*(Tv/QT + 1)/2, Bv), 256, SMEM_ATTN_BYTES>>>(mask);
    merge_kernel<<<(Mv*16)/256, 256>>>(out);
}

// round 7
// speedup vs baseline: 4.6195x; 1.5898x over previous
#include <cuda_runtime.h>
#include <cuda_bf16.h>
#include <math.h>

#define Bv 8
#define Tv 2048
#define Cv 1024
#define HSv 64
#define Mv (Bv*Tv)
#define QT 128
#define SLOTS 16

typedef unsigned long long u64;
typedef unsigned int u32;

// ---------- cp.async ----------
__device__ __forceinline__ void cp16(void* dst_smem, const void* src){
    unsigned d = (unsigned)__cvta_generic_to_shared(dst_smem);
    asm volatile("cp.async.cg.shared.global [%0], [%1], 16;" :: "r"(d), "l"(src));
}
#define CP_COMMIT() asm volatile("cp.async.commit_group;")
#define CP_WAIT1()  asm volatile("cp.async.wait_group 1;")
#define CP_WAIT0()  asm volatile("cp.async.wait_group 0;")

// ---------- mma.sync helpers ----------
__device__ __forceinline__ u32 smem_u32(const void* p){
    return (u32)__cvta_generic_to_shared(p);
}
__device__ __forceinline__ void ldsm_x4(u32 &r0,u32 &r1,u32 &r2,u32 &r3, u32 addr){
    asm volatile("ldmatrix.sync.aligned.m8n8.x4.shared.b16 {%0,%1,%2,%3}, [%4];"
        : "=r"(r0),"=r"(r1),"=r"(r2),"=r"(r3) : "r"(addr));
}
__device__ __forceinline__ void ldsm_x2(u32 &r0,u32 &r1, u32 addr){
    asm volatile("ldmatrix.sync.aligned.m8n8.x2.shared.b16 {%0,%1}, [%2];"
        : "=r"(r0),"=r"(r1) : "r"(addr));
}
__device__ __forceinline__ void ldsm_x2t(u32 &r0,u32 &r1, u32 addr){
    asm volatile("ldmatrix.sync.aligned.m8n8.x2.trans.shared.b16 {%0,%1}, [%2];"
        : "=r"(r0),"=r"(r1) : "r"(addr));
}
__device__ __forceinline__ void mma16816(float* d, const u32* a, const u32* b){
    asm volatile("mma.sync.aligned.m16n8k16.row.col.f32.bf16.bf16.f32 "
        "{%0,%1,%2,%3}, {%4,%5,%6,%7}, {%8,%9}, {%0,%1,%2,%3};"
        : "+f"(d[0]),"+f"(d[1]),"+f"(d[2]),"+f"(d[3])
        : "r"(a[0]),"r"(a[1]),"r"(a[2]),"r"(a[3]), "r"(b[0]),"r"(b[1]));
}

__device__ __forceinline__ void split_pair(float x, float y, u32 &h, u32 &lo){
    __nv_bfloat162 hh = __floats2bfloat162_rn(x, y);
    float2 fo = __bfloat1622float2(hh);
    __nv_bfloat162 ll = __floats2bfloat162_rn(x - fo.x, y - fo.y);
    h  = *(u32*)&hh;
    lo = *(u32*)&ll;
}

// ---------- scratch ----------
// g_abuf: [0]=q_hi [1]=q_lo [2]=k_hi [3]=k_lo [4]=v_hi [5]=v_lo, each [Mv][64] bf16
__device__ __nv_bfloat16 g_abuf[6*(size_t)Mv*HSv];
__device__ float g_pacc[(size_t)SLOTS*Mv*HSv];
__device__ float g_pm[SLOTS*Mv];
__device__ float g_pl[SLOTS*Mv];
__device__ __nv_bfloat16 g_wt[3*2*64*1024];   // [z][hi/lo][n][k]

// =====================================================================
// Kernel 0: transpose + bf16-split weights
// =====================================================================
__global__ __launch_bounds__(256) void prep_wt(
    const float* __restrict__ Wq, const float* __restrict__ Wk,
    const float* __restrict__ Wv)
{
    int id = blockIdx.x*256 + threadIdx.x;
    int z = id >> 16; int rem = id & 65535;
    int n = rem >> 10; int k = rem & 1023;
    const float* W = (z==0) ? Wq : (z==1) ? Wk : Wv;
    float w = W[k*64 + n];
    __nv_bfloat16 h = __float2bfloat16(w);
    float r = w - __bfloat162float(h);
    g_wt[(size_t)(z*2+0)*65536 + n*1024 + k] = h;
    g_wt[(size_t)(z*2+1)*65536 + n*1024 + k] = __float2bfloat16(r);
}

// =====================================================================
// Kernel 1: HMMA split-bf16 projection; outputs split-bf16 q/k/v.
// Q pre-scaled by 0.125 (exact).
// =====================================================================
#define KCH 64
#define NCHUNK (Cv/KCH)
#define A_HI 0
#define A_LO 36864
#define B_HI 73728
#define B_LO 110592
#define PROJ_SMEM 147456

__device__ __forceinline__ void cvt_split4(float4 a, uint2 &hi, uint2 &lo){
    __nv_bfloat162 h01 = __floats2bfloat162_rn(a.x, a.y);
    __nv_bfloat162 h23 = __floats2bfloat162_rn(a.z, a.w);
    float2 f01 = __bfloat1622float2(h01);
    float2 f23 = __bfloat1622float2(h23);
    __nv_bfloat162 l01 = __floats2bfloat162_rn(a.x - f01.x, a.y - f01.y);
    __nv_bfloat162 l23 = __floats2bfloat162_rn(a.z - f23.x, a.w - f23.y);
    hi.x = *(u32*)&h01; hi.y = *(u32*)&h23;
    lo.x = *(u32*)&l01; lo.y = *(u32*)&l23;
}

__global__ __launch_bounds__(256) void proj_mma(
    const float* __restrict__ qv, const float* __restrict__ kvec,
    const float* __restrict__ vv)
{
    extern __shared__ __align__(128) char smc[];
    const int t   = threadIdx.x;
    const int wid = t >> 5;
    const int l   = t & 31;
    const int z   = blockIdx.y;
    const int m0  = blockIdx.x * 128;
    const float* A = (z==0) ? qv : (z==1) ? kvec : vv;

    const u32 sbase = smem_u32(smc);
    const int wm = wid >> 1;
    const int wn = wid & 1;

    const int arow  = (l & 15);
    const int acol8 = (l >> 4) * 8;
    const int brow  = (l & 7);
    const int bk8   = ((l >> 3) & 1) * 8;

    auto loadB = [&](int it2){
        int slot = it2 & 3; int k0 = it2 * KCH;
        #pragma unroll
        for (int i = 0; i < 4; i++){
            int idx = t + i*256;
            int term = idx >> 9;
            int rem = idx & 511;
            int n = rem >> 3, c = rem & 7;
            cp16(smc + (term ? B_LO : B_HI) + slot*9216 + n*144 + c*16,
                 g_wt + (size_t)(z*2+term)*65536 + n*1024 + k0 + c*8);
        }
    };

    float4 aPre[8];
    auto loadA = [&](int it2){
        int k0 = it2 * KCH;
        #pragma unroll
        for (int i = 0; i < 8; i++){
            int idx = t + i*256; int r = idx >> 4, c4 = idx & 15;
            aPre[i] = *(const float4*)(A + (size_t)(m0 + r)*Cv + k0 + c4*4);
        }
    };

    loadA(0);
    loadB(0); CP_COMMIT();
    loadB(1); CP_COMMIT();

    float D[2][4][4];
    #pragma unroll
    for (int mt = 0; mt < 2; mt++)
        #pragma unroll
        for (int nc = 0; nc < 4; nc++)
            #pragma unroll
            for (int e = 0; e < 4; e++) D[mt][nc][e] = 0.f;

    #pragma unroll 1
    for (int it = 0; it < NCHUNK; it++){
        CP_WAIT1();
        const int buf = it & 1;
        const int slot = it & 3;

        #pragma unroll
        for (int i = 0; i < 8; i++){
            int idx = t + i*256; int r = idx >> 4, c4 = idx & 15;
            uint2 hi, lo; cvt_split4(aPre[i], hi, lo);
            *(uint2*)(smc + A_HI + buf*18432 + r*144 + c4*8) = hi;
            *(uint2*)(smc + A_LO + buf*18432 + r*144 + c4*8) = lo;
        }
        __syncthreads();

        if (it + 1 < NCHUNK) loadA(it + 1);
        if (it + 2 < NCHUNK){ loadB(it + 2); CP_COMMIT(); }

        const u32 aHiB = sbase + A_HI + buf*18432;
        const u32 aLoB = sbase + A_LO + buf*18432;
        const u32 bHiB = sbase + B_HI + slot*9216;
        const u32 bLoB = sbase + B_LO + slot*9216;

        #pragma unroll
        for (int ks = 0; ks < 4; ks++){
            u32 AH[2][4], AL[2][4], BH[4][2], BL[4][2];
            #pragma unroll
            for (int mt = 0; mt < 2; mt++){
                u32 ao = (u32)((wm*32 + mt*16 + arow)*144 + (ks*16 + acol8)*2);
                ldsm_x4(AH[mt][0], AH[mt][1], AH[mt][2], AH[mt][3], aHiB + ao);
                ldsm_x4(AL[mt][0], AL[mt][1], AL[mt][2], AL[mt][3], aLoB + ao);
            }
            #pragma unroll
            for (int nc = 0; nc < 4; nc++){
                u32 bo = (u32)((wn*32 + nc*8 + brow)*144 + (ks*16 + bk8)*2);
                ldsm_x2(BH[nc][0], BH[nc][1], bHiB + bo);
                ldsm_x2(BL[nc][0], BL[nc][1], bLoB + bo);
            }
            #pragma unroll
            for (int mt = 0; mt < 2; mt++)
                #pragma unroll
                for (int nc = 0; nc < 4; nc++){
                    mma16816(D[mt][nc], AH[mt], BH[nc]);
                    mma16816(D[mt][nc], AH[mt], BL[nc]);
                    mma16816(D[mt][nc], AL[mt], BH[nc]);
                }
        }
        __syncthreads();
    }

    // write split-bf16 outputs (Q scaled by 0.125)
    const float sc = (z == 0) ? 0.125f : 1.0f;
    __nv_bfloat16* ghi = g_abuf + (size_t)(z*2+0)*Mv*HSv;
    __nv_bfloat16* glo = g_abuf + (size_t)(z*2+1)*Mv*HSv;
    #pragma unroll
    for (int mt = 0; mt < 2; mt++){
        int row = m0 + wm*32 + mt*16 + (l >> 2);
        #pragma unroll
        for (int nc = 0; nc < 4; nc++){
            int col = wn*32 + nc*8 + (l & 3)*2;
            u32 h0, l0, h1, l1;
            split_pair(D[mt][nc][0]*sc, D[mt][nc][1]*sc, h0, l0);
            split_pair(D[mt][nc][2]*sc, D[mt][nc][3]*sc, h1, l1);
            *(u32*)(ghi + (size_t)row*HSv + col)     = h0;
            *(u32*)(glo + (size_t)row*HSv + col)     = l0;
            *(u32*)(ghi + (size_t)(row+8)*HSv + col) = h1;
            *(u32*)(glo + (size_t)(row+8)*HSv + col) = l1;
        }
    }
}

// =====================================================================
// Kernel 2: HMMA attention. CTA = (qb, s) triangular x batch.
// 8 warps, warp owns 16 q-rows x full 128-key chunk.
// GEMM1: S = Q.K^T (3-term split). Single-shot softmax. GEMM2: O = P.V.
// =====================================================================
#define AQH 0
#define AQL 18432
#define AKH 36864
#define AKL 55296
#define AVH 73728
#define AVL 92160
#define AMSK 110592
#define ATTN_SMEM (110592 + 512)

__global__ __launch_bounds__(256, 1) void attn_mma(const int* __restrict__ mask)
{
    extern __shared__ __align__(128) char smc[];
    const u32 sbase = smem_u32(smc);
    int* Msk = (int*)(smc + AMSK);

    int x = blockIdx.x;
    int qb = (int)((sqrtf(8.f*x + 1.f) - 1.f) * 0.5f);
    while ((qb+1)*(qb+2)/2 <= x) qb++;
    while (qb*(qb+1)/2 > x) qb--;
    const int s = x - qb*(qb+1)/2;

    const int b  = blockIdx.y;
    const int t  = threadIdx.x;
    const int w  = t >> 5;
    const int l  = t & 31;
    const int bT = b*Tv;
    const int row0 = qb*QT;
    const int kstart = s*128;

    // ---- async loads: group A = K(hi,lo), Q(hi,lo), mask; group B = V(hi,lo)
    auto load_arr = [&](int aa, int dst_off, int src_row0){
        const __nv_bfloat16* src = g_abuf + (size_t)aa*Mv*HSv + (size_t)(bT + src_row0)*HSv;
        #pragma unroll
        for (int i = 0; i < 4; i++){
            int idx = t + i*256; int r = idx >> 3, c = idx & 7;
            cp16(smc + dst_off + r*144 + c*16, src + r*64 + c*8);
        }
    };
    load_arr(2, AKH, kstart);
    load_arr(3, AKL, kstart);
    load_arr(0, AQH, row0);
    load_arr(1, AQL, row0);
    if (t < 32) cp16(&Msk[t*4], mask + bT + kstart + t*4);
    CP_COMMIT();
    load_arr(4, AVH, kstart);
    load_arr(5, AVL, kstart);
    CP_COMMIT();

    const int arow  = (l & 15);
    const int acol8 = (l >> 4) * 8;
    const int brow  = (l & 7);
    const int bk8   = ((l >> 3) & 1) * 8;
    const int vofs  = (l & 15) * 144;       // trans ldmatrix row offset

    CP_WAIT1();
    __syncthreads();

    // ---- Q fragments (persistent) ----
    u32 QH4[4][4], QL4[4][4];
    #pragma unroll
    for (int ks = 0; ks < 4; ks++){
        u32 ao = (u32)((w*16 + arow)*144 + (ks*16 + acol8)*2);
        ldsm_x4(QH4[ks][0], QH4[ks][1], QH4[ks][2], QH4[ks][3], sbase + AQH + ao);
        ldsm_x4(QL4[ks][0], QL4[ks][1], QL4[ks][2], QL4[ks][3], sbase + AQL + ao);
    }

    // ---- GEMM1 ----
    float S[16][4];
    #pragma unroll
    for (int nt = 0; nt < 16; nt++)
        #pragma unroll
        for (int e = 0; e < 4; e++) S[nt][e] = 0.f;

    #pragma unroll
    for (int ks = 0; ks < 4; ks++){
        #pragma unroll
        for (int nt = 0; nt < 16; nt++){
            u32 bo = (u32)((nt*8 + brow)*144 + (ks*16 + bk8)*2);
            u32 BH0, BH1, BL0, BL1;
            ldsm_x2(BH0, BH1, sbase + AKH + bo);
            ldsm_x2(BL0, BL1, sbase + AKL + bo);
            u32 BH[2] = {BH0, BH1}, BL[2] = {BL0, BL1};
            mma16816(S[nt], QH4[ks], BH);
            mma16816(S[nt], QH4[ks], BL);
            mma16816(S[nt], QL4[ks], BH);
        }
    }

    // ---- mask + softmax (single-shot) ----
    const int g  = l >> 2;
    const int qx = l & 3;
    const int r0g = row0 + w*16 + g;     // c0,c1 rows (local to batch)
    const int r1g = r0g + 8;             // c2,c3 rows

    float m0 = -INFINITY, m1 = -INFINITY;
    #pragma unroll
    for (int nt = 0; nt < 16; nt++){
        int kb = kstart + nt*8 + qx*2;   // local key index of c0
        bool va = (kb   <= r0g) && Msk[nt*8 + qx*2];
        bool vb = (kb+1 <= r0g) && Msk[nt*8 + qx*2 + 1];
        bool vc = (kb   <= r1g) && Msk[nt*8 + qx*2];
        bool vd = (kb+1 <= r1g) && Msk[nt*8 + qx*2 + 1];
        S[nt][0] = va ? S[nt][0] : -INFINITY;
        S[nt][1] = vb ? S[nt][1] : -INFINITY;
        S[nt][2] = vc ? S[nt][2] : -INFINITY;
        S[nt][3] = vd ? S[nt][3] : -INFINITY;
        m0 = fmaxf(m0, fmaxf(S[nt][0], S[nt][1]));
        m1 = fmaxf(m1, fmaxf(S[nt][2], S[nt][3]));
    }
    m0 = fmaxf(m0, __shfl_xor_sync(0xFFFFFFFFu, m0, 1));
    m0 = fmaxf(m0, __shfl_xor_sync(0xFFFFFFFFu, m0, 2));
    m1 = fmaxf(m1, __shfl_xor_sync(0xFFFFFFFFu, m1, 1));
    m1 = fmaxf(m1, __shfl_xor_sync(0xFFFFFFFFu, m1, 2));
    float mn0 = fmaxf(m0, -1e30f), mn1 = fmaxf(m1, -1e30f);

    float l0 = 0.f, l1 = 0.f;
    #pragma unroll
    for (int nt = 0; nt < 16; nt++){
        S[nt][0] = __expf(S[nt][0] - mn0);
        S[nt][1] = __expf(S[nt][1] - mn0);
        S[nt][2] = __expf(S[nt][2] - mn1);
        S[nt][3] = __expf(S[nt][3] - mn1);
        l0 += S[nt][0] + S[nt][1];
        l1 += S[nt][2] + S[nt][3];
    }
    l0 += __shfl_xor_sync(0xFFFFFFFFu, l0, 1);
    l0 += __shfl_xor_sync(0xFFFFFFFFu, l0, 2);
    l1 += __shfl_xor_sync(0xFFFFFFFFu, l1, 1);
    l1 += __shfl_xor_sync(0xFFFFFFFFu, l1, 2);

    if (qx == 0){
        g_pm[s*Mv + bT + r0g] = m0;  g_pl[s*Mv + bT + r0g] = l0;
        g_pm[s*Mv + bT + r1g] = m1;  g_pl[s*Mv + bT + r1g] = l1;
    }

    // ---- GEMM2: O = P . V ----
    CP_WAIT0();
    __syncthreads();

    float O[8][4];
    #pragma unroll
    for (int nb = 0; nb < 8; nb++)
        #pragma unroll
        for (int e = 0; e < 4; e++) O[nb][e] = 0.f;

    #pragma unroll
    for (int ks = 0; ks < 8; ks++){
        u32 Ph[4], Pl[4];
        split_pair(S[2*ks][0],   S[2*ks][1],   Ph[0], Pl[0]);
        split_pair(S[2*ks][2],   S[2*ks][3],   Ph[1], Pl[1]);
        split_pair(S[2*ks+1][0], S[2*ks+1][1], Ph[2], Pl[2]);
        split_pair(S[2*ks+1][2], S[2*ks+1][3], Ph[3], Pl[3]);
        #pragma unroll
        for (int nb = 0; nb < 8; nb++){
            u32 bo = (u32)(ks*16*144 + vofs + nb*16);
            u32 BH0, BH1, BL0, BL1;
            ldsm_x2t(BH0, BH1, sbase + AVH + bo);
            ldsm_x2t(BL0, BL1, sbase + AVL + bo);
            u32 BH[2] = {BH0, BH1}, BL[2] = {BL0, BL1};
            mma16816(O[nb], Ph, BH);
            mma16816(O[nb], Ph, BL);
            mma16816(O[nb], Pl, BH);
        }
    }

    // ---- write unnormalized partials ----
    #pragma unroll
    for (int nb = 0; nb < 8; nb++){
        int col = nb*8 + qx*2;
        *(float2*)(g_pacc + ((size_t)s*Mv + bT + r0g)*HSv + col) = make_float2(O[nb][0], O[nb][1]);
        *(float2*)(g_pacc + ((size_t)s*Mv + bT + r1g)*HSv + col) = make_float2(O[nb][2], O[nb][3]);
    }
}

// =====================================================================
// Kernel 3: merge variable-count partials
// =====================================================================
__global__ __launch_bounds__(256) void merge_kernel(float* __restrict__ out)
{
    int gid = blockIdx.x * blockDim.x + threadIdx.x;
    int row = gid >> 4, c4 = gid & 15;
    const int ns = ((row & (Tv-1)) >> 7) + 1;

    float M = -INFINITY;
    for (int s2 = 0; s2 < ns; s2++) M = fmaxf(M, g_pm[s2*Mv + row]);

    float4 o = make_float4(0.f, 0.f, 0.f, 0.f);
    float denom = 0.f;
    if (M > -INFINITY){
        for (int s2 = 0; s2 < ns; s2++){
            float w = __expf(g_pm[s2*Mv + row] - M);
            denom += g_pl[s2*Mv + row] * w;
            float4 a = ((const float4*)g_pacc)[((size_t)s2*Mv + row)*16 + c4];
            o.x += a.x*w; o.y += a.y*w; o.z += a.z*w; o.w += a.w*w;
        }
        float inv = (denom > 0.f) ? 1.f/denom : 0.f;
        o.x *= inv; o.y *= inv; o.z *= inv; o.w *= inv;
    }
    ((float4*)out)[gid] = o;
}

// =====================================================================
extern "C" void kernel_launch(void* const* d_in, const int* in_sizes, int n_in,
                              void* d_out, int out_size)
{
    const float* q_vec = (const float*)d_in[0];
    const float* k_vec = (const float*)d_in[1];
    const float* v_vec = (const float*)d_in[2];
    const int*   mask  = (const int*)  d_in[3];
    const float* Wq    = (const float*)d_in[4];
    const float* Wk    = (const float*)d_in[5];
    const float* Wv    = (const float*)d_in[6];
    float* out = (float*)d_out;

    cudaFuncSetAttribute(proj_mma,
        cudaFuncAttributeMaxDynamicSharedMemorySize, PROJ_SMEM);
    cudaFuncSetAttribute(attn_mma,
        cudaFuncAttributeMaxDynamicSharedMemorySize, ATTN_SMEM);

    prep_wt<<<768, 256>>>(Wq, Wk, Wv);
    proj_mma<<<dim3(Mv/128, 3), 256, PROJ_SMEM>>>(q_vec, k_vec, v_vec);
    attn_mma<<<dim3((Tv/QT)*(Tv/QT + 1)/2, Bv), 256, ATTN_SMEM>>>(mask);
    merge_kernel<<<(Mv*16)/256, 256>>>(out);
}